// round 4
// baseline (speedup 1.0000x reference)
#include <cuda_runtime.h>
#include <cuda_bf16.h>
#include <math.h>
#include <stdint.h>

#define NQ 16384
#define NC 8192
#define DD 256
#define ZELEMS 4194304
#define LOSS_OFF 4194304
#define PERP_OFF 4194305
#define UNIQ_OFF 4194306
#define IDX_OFF  4194307

#define QS   18.0f                   // int8 quant scale (7-sigma clip)
#define C2S  0.006172839506172839f   // 2 / (QS*QS)
#define MARGIN 6.0f

// ---------------- device scratch (no allocs allowed) ----------------
__device__ float   g_cnorm[NC];
__device__ int     g_counts[NC];
__device__ int     g_idx[NQ];
__device__ float   g_lpart[16384];
__device__ int8_t  g_w8[NC * DD];     // int8 codebook [code][k]
__device__ float   g_zT[NQ * DD];     // channel-last queries (for rescore)
__device__ float   g_bm8[1024 * NQ];  // per-8-code bin minima, bin-major

// ---------------- PTX helpers (family-wide, sm_80-era) ----------------
__device__ __forceinline__ uint32_t s2u(const void* p) {
    uint32_t a;
    asm("{ .reg .u64 t; cvta.to.shared.u64 t, %1; cvt.u32.u64 %0, t; }" : "=r"(a) : "l"(p));
    return a;
}
__device__ __forceinline__ void ldsm4(uint32_t addr, uint32_t& r0, uint32_t& r1,
                                      uint32_t& r2, uint32_t& r3) {
    asm volatile("ldmatrix.sync.aligned.m8n8.x4.shared.b16 {%0,%1,%2,%3}, [%4];"
                 : "=r"(r0), "=r"(r1), "=r"(r2), "=r"(r3) : "r"(addr));
}
__device__ __forceinline__ void imma16832(int* d, const uint32_t* a, uint32_t b0, uint32_t b1) {
    asm volatile(
        "mma.sync.aligned.m16n8k32.row.col.s32.s8.s8.s32 "
        "{%0,%1,%2,%3},{%4,%5,%6,%7},{%8,%9},{%0,%1,%2,%3};"
        : "+r"(d[0]), "+r"(d[1]), "+r"(d[2]), "+r"(d[3])
        : "r"(a[0]), "r"(a[1]), "r"(a[2]), "r"(a[3]), "r"(b0), "r"(b1));
}
#define CPASYNC(dst, src) \
    asm volatile("cp.async.cg.shared.global [%0], [%1], 16;" :: "r"(dst), "l"(src))
#define CPCOMMIT() asm volatile("cp.async.commit_group;")
#define CPWAIT(n)  asm volatile("cp.async.wait_group %0;" :: "n"(n))

// smem layout: A 32K | B0 32K | B1 32K | cn 32K
#define SM_A  0
#define SM_B0 32768
#define SM_B1 65536
#define SM_CN 98304
#define SMEM_SZ 131072

// ---------------- prep kernels ----------------
__global__ void k_zero() {
    int t = blockIdx.x * blockDim.x + threadIdx.x;
    if (t < NC) g_counts[t] = 0;
}

__global__ void k_cnorm(const float* __restrict__ w) {
    int warp = threadIdx.x >> 5, lane = threadIdx.x & 31;
    int c = blockIdx.x * 8 + warp;
    const float* row = w + c * DD;
    float s = 0.f;
#pragma unroll
    for (int j = 0; j < 8; j++) { float v = row[lane + j * 32]; s += v * v; }
#pragma unroll
    for (int off = 16; off; off >>= 1) s += __shfl_xor_sync(0xffffffffu, s, off);
    if (lane == 0) g_cnorm[c] = s;
}

__device__ __forceinline__ int8_t q8(float v) {
    int q = __float2int_rn(v * QS);
    return (int8_t)max(-127, min(127, q));
}

__global__ void k_w8(const float* __restrict__ w) {
    int t = blockIdx.x * 256 + threadIdx.x;     // grid 2048 -> 524288 float4
    float4 v = ((const float4*)w)[t];
    char4 o;
    o.x = q8(v.x); o.y = q8(v.y); o.z = q8(v.z); o.w = q8(v.w);
    ((char4*)g_w8)[t] = o;
}

__global__ void k_zt(const float* __restrict__ z) {
    __shared__ float tile[32][33];
    int s0 = blockIdx.x * 32, c0 = blockIdx.y * 32, b = blockIdx.z;
    int tx = threadIdx.x, ty = threadIdx.y;
#pragma unroll
    for (int r = 0; r < 4; r++)
        tile[ty + r * 8][tx] = z[b * 1048576 + (c0 + ty + r * 8) * 4096 + s0 + tx];
    __syncthreads();
#pragma unroll
    for (int r = 0; r < 4; r++)
        g_zT[(b * 4096 + s0 + ty + r * 8) * DD + c0 + tx] = tile[tx][ty + r * 8];
}

// ---------------- int8 IMMA distance GEMM + per-8-code bin minima ----------------
// grid = 128 CTAs (one 128-query slab), 256 thr; 64 code tiles of 128 codes.
__global__ void __launch_bounds__(256, 1) k_tc(const float* __restrict__ z) {
    extern __shared__ char smem[];
    uint32_t sb = s2u(smem);
    float* cn_s = (float*)(smem + SM_CN);

    int tid = threadIdx.x, lane = tid & 31, wid = tid >> 5;
    int qbase = blockIdx.x * 128;
    int b = blockIdx.x >> 5, s0 = (blockIdx.x & 31) * 128;
    const float* zb = z + b * 1048576 + s0;

    // prefetch B tile 0 (32 KB)
    {
        const char* gs = (const char*)g_w8;
#pragma unroll
        for (int i = 0; i < 8; i++) {
            int e = tid + i * 256;
            int n = e >> 4, kc = e & 15;
            CPASYNC(sb + SM_B0 + n * 256 + ((kc ^ (n & 7)) << 4), gs + n * 256 + kc * 16);
        }
        CPCOMMIT();
    }
    // cnorm -> smem
    {
        const float4* src = (const float4*)g_cnorm;
        float4* dst = (float4*)cn_s;
        for (int i = tid; i < 2048; i += 256) dst[i] = src[i];
    }
    // A fill: 128 q x 256 k int8, swizzled (chunk ^ (row&7))
    for (int e = tid; e < 8192; e += 256) {
        int c = e >> 5, r4 = (e & 31) * 4;
        float4 v = *(const float4*)(zb + c * 4096 + r4);
        int hi = c >> 4, lo = c & 15;
        float vv[4] = {v.x, v.y, v.z, v.w};
#pragma unroll
        for (int j = 0; j < 4; j++) {
            int row = r4 + j;
            *(int8_t*)(smem + SM_A + row * 256 + ((hi ^ (row & 7)) << 4) + lo) = q8(vv[j]);
        }
    }
    __syncthreads();

    int wm = (wid & 3) * 32, wn = (wid >> 2) * 64;
    int aR = wm + (lane & 15);
    int aC = lane >> 4;             // +chunk for upper half-warp
    int bR = wn + (lane & 7) + ((lane >> 4) << 3);
    int bC = (lane >> 3) & 1;
    int aSw = (aR & 7);

    for (int t = 0; t < 64; t++) {
        if (t + 1 < 64) {
            const char* gs = (const char*)g_w8 + (size_t)(t + 1) * 32768;
            uint32_t bb = sb + (((t + 1) & 1) ? SM_B1 : SM_B0);
#pragma unroll
            for (int i = 0; i < 8; i++) {
                int e = tid + i * 256;
                int n = e >> 4, kc = e & 15;
                CPASYNC(bb + n * 256 + ((kc ^ (n & 7)) << 4), gs + n * 256 + kc * 16);
            }
            CPCOMMIT();
            CPWAIT(1);
        } else {
            CPWAIT(0);
        }
        __syncthreads();

        uint32_t sB = sb + ((t & 1) ? SM_B1 : SM_B0);
        int d[2][8][4];
#pragma unroll
        for (int mi = 0; mi < 2; mi++)
#pragma unroll
            for (int ni = 0; ni < 8; ni++)
#pragma unroll
                for (int u = 0; u < 4; u++) d[mi][ni][u] = 0;

#pragma unroll
        for (int ks = 0; ks < 8; ks++) {
            int cA = 2 * ks + aC;
            uint32_t a0[4], a1[4];
            ldsm4(sb + SM_A + aR * 256 + ((cA ^ aSw) << 4), a0[0], a0[1], a0[2], a0[3]);
            ldsm4(sb + SM_A + (aR + 16) * 256 + ((cA ^ aSw) << 4), a1[0], a1[1], a1[2], a1[3]);
            int cB = 2 * ks + bC;
#pragma unroll
            for (int j = 0; j < 4; j++) {
                int rB = bR + 16 * j;
                uint32_t b0, b1, b2, b3;
                ldsm4(sB + rB * 256 + ((cB ^ (rB & 7)) << 4), b0, b1, b2, b3);
                imma16832(d[0][2 * j], a0, b0, b1);
                imma16832(d[0][2 * j + 1], a0, b2, b3);
                imma16832(d[1][2 * j], a1, b0, b1);
                imma16832(d[1][2 * j + 1], a1, b2, b3);
            }
        }

        // epilogue: dist = cn - C2S*dot_int; per-8-col bin min; lanes%4==0 write
#pragma unroll
        for (int mi = 0; mi < 2; mi++) {
#pragma unroll
            for (int ni = 0; ni < 8; ni++) {
                float2 cn2 = *(float2*)&cn_s[t * 128 + wn + ni * 8 + (lane & 3) * 2];
                float v0 = fminf(cn2.x - (float)d[mi][ni][0] * C2S,
                                 cn2.y - (float)d[mi][ni][1] * C2S);
                float v1 = fminf(cn2.x - (float)d[mi][ni][2] * C2S,
                                 cn2.y - (float)d[mi][ni][3] * C2S);
                v0 = fminf(v0, __shfl_xor_sync(0xffffffffu, v0, 1));
                v0 = fminf(v0, __shfl_xor_sync(0xffffffffu, v0, 2));
                v1 = fminf(v1, __shfl_xor_sync(0xffffffffu, v1, 1));
                v1 = fminf(v1, __shfl_xor_sync(0xffffffffu, v1, 2));
                if ((lane & 3) == 0) {
                    int bin = t * 16 + (wn >> 3) + ni;
                    int q0 = qbase + wm + mi * 16 + (lane >> 2);
                    g_bm8[(size_t)bin * NQ + q0] = v0;
                    g_bm8[(size_t)bin * NQ + q0 + 8] = v1;
                }
            }
        }
        __syncthreads();
    }
}

// ---------------- exact rescore of candidate bins ----------------
__global__ void k_rescore(const float* __restrict__ w) {
    int q = blockIdx.x * 128 + threadIdx.x;
    float m = __int_as_float(0x7f800000);
#pragma unroll 8
    for (int i = 0; i < 1024; i++) m = fminf(m, g_bm8[(size_t)i * NQ + q]);
    float thr = m + MARGIN;

    float best = __int_as_float(0x7f800000);
    int bi = 0;
    const float4* zq4 = (const float4*)(g_zT + (size_t)q * DD);
    for (int i = 0; i < 1024; i++) {
        if (g_bm8[(size_t)i * NQ + q] <= thr) {
            float acc[8];
#pragma unroll
            for (int k = 0; k < 8; k++) acc[k] = 0.f;
            const float4* wr = (const float4*)(w + (size_t)i * 8 * DD);
            for (int c4 = 0; c4 < 64; c4++) {
                float4 zv = __ldg(&zq4[c4]);
#pragma unroll
                for (int k = 0; k < 8; k++) {
                    float4 wv = __ldg(&wr[k * 64 + c4]);
                    acc[k] = fmaf(zv.x, wv.x, acc[k]);
                    acc[k] = fmaf(zv.y, wv.y, acc[k]);
                    acc[k] = fmaf(zv.z, wv.z, acc[k]);
                    acc[k] = fmaf(zv.w, wv.w, acc[k]);
                }
            }
#pragma unroll
            for (int k = 0; k < 8; k++) {
                int c = i * 8 + k;
                float sc = g_cnorm[c] - 2.f * acc[k];
                if (sc < best) { best = sc; bi = c; }
            }
        }
    }
    g_idx[q] = bi;
    atomicAdd(&g_counts[bi], 1);
}

// ---------------- gather + straight-through + loss partials ----------------
__global__ void k_gather(const float* __restrict__ z, const float* __restrict__ w,
                         float* __restrict__ out) {
    int o = blockIdx.x * 256 + threadIdx.x;
    int s = o & 4095;
    int c = (o >> 12) & 255;
    int b = o >> 20;
    int n = b * 4096 + s;
    int id = g_idx[n];
    float zv = z[o];
    float wv = __ldg(w + id * DD + c);
    float d = wv - zv;
    out[o] = zv + d;

    float v = d * d;
#pragma unroll
    for (int off = 16; off; off >>= 1) v += __shfl_xor_sync(0xffffffffu, v, off);
    __shared__ float red[8];
    if ((threadIdx.x & 31) == 0) red[threadIdx.x >> 5] = v;
    __syncthreads();
    if (threadIdx.x == 0) {
        float tsum = 0.f;
#pragma unroll
        for (int i = 0; i < 8; i++) tsum += red[i];
        g_lpart[blockIdx.x] = tsum;
    }
}

__global__ void k_idxout(float* __restrict__ out) {
    int t = blockIdx.x * blockDim.x + threadIdx.x;
    if (t < NQ) out[IDX_OFF + t] = (float)g_idx[t];
}

__global__ void k_final(float* __restrict__ out) {
    __shared__ double ds[32];
    __shared__ float es[32];
    __shared__ int us[32];
    int t = threadIdx.x, lane = t & 31, warp = t >> 5;

    double lsum = 0.0;
    for (int i = t; i < 16384; i += 1024) lsum += (double)g_lpart[i];

    float ent = 0.f; int uniq = 0;
    for (int c = t; c < NC; c += 1024) {
        int cnt = g_counts[c];
        float p = (float)cnt * (1.0f / 16384.0f);
        ent += p * logf(p + 1e-10f);
        uniq += (cnt > 0);
    }
#pragma unroll
    for (int off = 16; off; off >>= 1) {
        lsum += __shfl_xor_sync(0xffffffffu, lsum, off);
        ent += __shfl_xor_sync(0xffffffffu, ent, off);
        uniq += __shfl_xor_sync(0xffffffffu, uniq, off);
    }
    if (lane == 0) { ds[warp] = lsum; es[warp] = ent; us[warp] = uniq; }
    __syncthreads();
    if (t == 0) {
        double L = 0.0; float E = 0.f; int U = 0;
        for (int i = 0; i < 32; i++) { L += ds[i]; E += es[i]; U += us[i]; }
        out[LOSS_OFF] = 0.25f * (float)(L * (1.0 / 4194304.0));
        out[PERP_OFF] = expf(-E);
        out[UNIQ_OFF] = (float)U;
    }
}

// ---------------- launch ----------------
extern "C" void kernel_launch(void* const* d_in, const int* in_sizes, int n_in,
                              void* d_out, int out_size) {
    const float* z = (const float*)d_in[0];
    const float* w = (const float*)d_in[1];
    float* out = (float*)d_out;

    cudaFuncSetAttribute(k_tc, cudaFuncAttributeMaxDynamicSharedMemorySize, SMEM_SZ);

    k_zero<<<8, 1024>>>();
    k_cnorm<<<NC / 8, 256>>>(w);
    k_w8<<<2048, 256>>>(w);
    k_zt<<<dim3(128, 8, 4), dim3(32, 8)>>>(z);
    k_tc<<<NQ / 128, 256, SMEM_SZ>>>(z);
    k_rescore<<<NQ / 128, 128>>>(w);
    k_gather<<<ZELEMS / 256, 256>>>(z, w, out);
    k_idxout<<<16, 1024>>>(out);
    k_final<<<1, 1024>>>(out);
}